// round 17
// baseline (speedup 1.0000x reference)
#include <cuda_runtime.h>
#include <cuda_fp16.h>
#include <cstdint>

#define NE 8
#define NT 2048
#define ND 2048
#define NH 4096

// ---------------- scratch (static __device__, allocation-free) ----------------
__device__ __half g_x16[(long long)NE * NT * ND];
__device__ __half g_w1 [(long long)NE * ND * NH];
__device__ __half g_w3 [(long long)NE * ND * NH];
__device__ __half g_w2 [(long long)NE * NH * ND];
__device__ __half g_h16[(long long)NE * NT * NH];

// ---------------- cross-ticket control (zeroed by reset kernel each call) -------
__device__ int g_ticket;
__device__ int g_cnt[NE];     // conv completion per expert (target 80)

#define TK_PER_E (16 + 64 + 1024)        // 1104
#define TK_W2    1024
#define TK_TOT   (NE * TK_PER_E + TK_W2) // 9856

// ---------------- PTX helpers (base-target sm_80+) ----------------
__device__ __forceinline__ void cp16s(uint32_t dst, const void* src) {
    asm volatile("cp.async.cg.shared.global [%0], [%1], 16;" :: "r"(dst), "l"(src));
}
__device__ __forceinline__ void ldsm4(uint32_t* r, uint32_t a) {
    asm volatile("ldmatrix.sync.aligned.m8n8.x4.shared.b16 {%0,%1,%2,%3}, [%4];"
                 : "=r"(r[0]), "=r"(r[1]), "=r"(r[2]), "=r"(r[3]) : "r"(a));
}
__device__ __forceinline__ void ldsm4t(uint32_t* r, uint32_t a) {
    asm volatile("ldmatrix.sync.aligned.m8n8.x4.trans.shared.b16 {%0,%1,%2,%3}, [%4];"
                 : "=r"(r[0]), "=r"(r[1]), "=r"(r[2]), "=r"(r[3]) : "r"(a));
}
__device__ __forceinline__ void mma16816(float* d, const uint32_t* a, const uint32_t* b) {
    asm volatile(
        "mma.sync.aligned.m16n8k16.row.col.f32.f16.f16.f32 "
        "{%0,%1,%2,%3}, {%4,%5,%6,%7}, {%8,%9}, {%0,%1,%2,%3};"
        : "+f"(d[0]), "+f"(d[1]), "+f"(d[2]), "+f"(d[3])
        : "r"(a[0]), "r"(a[1]), "r"(a[2]), "r"(a[3]), "r"(b[0]), "r"(b[1]));
}

// 8-element fp32 -> fp16 convert unit (absolute unit index u)
__device__ __forceinline__ void conv8(const float4* __restrict__ src,
                                      __half2* __restrict__ dst, long long u) {
    float4 v0 = src[2 * u];
    float4 v1 = src[2 * u + 1];
    __half2 h[4];
    h[0] = __floats2half2_rn(v0.x, v0.y);
    h[1] = __floats2half2_rn(v0.z, v0.w);
    h[2] = __floats2half2_rn(v1.x, v1.y);
    h[3] = __floats2half2_rn(v1.z, v1.w);
    *(uint4*)(dst + 4 * u) = *(uint4*)h;
}

// ---------------- reset (graph-replay determinism) ----------------
__global__ void reset_kernel() {
    if (threadIdx.x == 0) g_ticket = 0;
    if (threadIdx.x < NE) g_cnt[threadIdx.x] = 0;
}

// ---------------- gemm13 tile body (identical math to R15) ----------------
__device__ __forceinline__ void gemm13_tile(int e, int m0, int n0, uint32_t sbase, int tid)
{
    const __half* pA  = g_x16 + (long long)e * NT * ND + (long long)m0 * ND;
    const __half* pB1 = g_w1  + (long long)e * ND * NH + n0;
    const __half* pB3 = g_w3  + (long long)e * ND * NH + n0;

    const int warp = tid >> 5, lane = tid & 31;
    const int wm = (warp & 1) * 64;
    const int wn = (warp >> 1) * 16;

    float acc1[4][2][4], acc3[4][2][4];
    #pragma unroll
    for (int i = 0; i < 4; i++)
        #pragma unroll
        for (int j = 0; j < 2; j++)
            #pragma unroll
            for (int r = 0; r < 4; r++) { acc1[i][j][r] = 0.f; acc3[i][j][r] = 0.f; }

    auto load_stage = [&](int slot, int k0) {
        const uint32_t sb = sbase + slot * 32768;
        #pragma unroll
        for (int i = 0; i < 4; i++) {
            int id = tid + i * 256;
            int row = id >> 3, c = id & 7;
            cp16s(sb + row * 128 + ((c ^ (row & 7)) << 4),
                  pA + (long long)row * ND + k0 + c * 8);
        }
        #pragma unroll
        for (int i = 0; i < 2; i++) {
            int id = tid + i * 256;
            int row = id >> 3, c = id & 7;
            long long go = (long long)(k0 + row) * NH + c * 8;
            uint32_t so = sb + 16384 + row * 128 + ((c ^ (row & 7)) << 4);
            cp16s(so,        pB1 + go);
            cp16s(so + 8192, pB3 + go);
        }
        asm volatile("cp.async.commit_group;" ::: "memory");
    };

    load_stage(0, 0);
    load_stage(1, 64);

    const int NKC = ND / 64;
    for (int ch = 0; ch < NKC; ch++) {
        asm volatile("cp.async.wait_group 1;" ::: "memory");
        __syncthreads();
        if (ch + 2 < NKC) load_stage((ch + 2) % 3, (ch + 2) * 64);
        else asm volatile("cp.async.commit_group;" ::: "memory");

        const uint32_t sb = sbase + (ch % 3) * 32768;
        #pragma unroll
        for (int ks = 0; ks < 4; ks++) {
            uint32_t av[4][4], b1[2][2], b3[2][2];
            {   // B loads first: latency overlaps the A-load issue sequence
                int kr = ks * 16 + (lane & 15);
                int nc = (wn >> 3) + (lane >> 4);
                uint32_t bd = sb + 16384 + kr * 128 + ((nc ^ (kr & 7)) << 4);
                uint32_t r[4];
                ldsm4t(r, bd);
                b1[0][0] = r[0]; b1[0][1] = r[1];
                b1[1][0] = r[2]; b1[1][1] = r[3];
                ldsm4t(r, bd + 8192);
                b3[0][0] = r[0]; b3[0][1] = r[1];
                b3[1][0] = r[2]; b3[1][1] = r[3];
            }
            #pragma unroll
            for (int mt = 0; mt < 4; mt++) {
                int row = wm + mt * 16 + (lane & 15);
                int cc  = ks * 2 + (lane >> 4);
                ldsm4(av[mt], sb + row * 128 + ((cc ^ (row & 7)) << 4));
            }
            #pragma unroll
            for (int mt = 0; mt < 4; mt++)
                #pragma unroll
                for (int nt = 0; nt < 2; nt++) {
                    mma16816(acc1[mt][nt], av[mt], b1[nt]);
                    mma16816(acc3[mt][nt], av[mt], b3[nt]);
                }
        }
    }

    #pragma unroll
    for (int mt = 0; mt < 4; mt++)
        #pragma unroll
        for (int nt = 0; nt < 2; nt++) {
            const int row = m0 + wm + mt * 16 + (lane >> 2);
            const int col = n0 + wn + nt * 8 + (lane & 3) * 2;
            const long long i0 = ((long long)e * NT + row) * NH + col;
            const long long i1 = i0 + 8LL * NH;
            const float a0 = acc1[mt][nt][0], a1 = acc1[mt][nt][1];
            const float a2 = acc1[mt][nt][2], a3 = acc1[mt][nt][3];
            const float v0 = acc3[mt][nt][0] * a0 / (1.f + __expf(-a0));
            const float v1 = acc3[mt][nt][1] * a1 / (1.f + __expf(-a1));
            const float v2 = acc3[mt][nt][2] * a2 / (1.f + __expf(-a2));
            const float v3 = acc3[mt][nt][3] * a3 / (1.f + __expf(-a3));
            *(__half2*)&g_h16[i0] = __floats2half2_rn(v0, v1);
            *(__half2*)&g_h16[i1] = __floats2half2_rn(v2, v3);
        }
}

// ---------------- persistent kernel A: conv(x,w1,w3) interleaved with gemm13 ------
// Ticket order per expert e: 16 x-conv | 64 w-conv | 1024 gemm13 tiles (spin on
// cnt[e]==80). Tail: 1024 w2-conv tickets (consumed by the gemm2 launch).
__global__ __launch_bounds__(256, 2)
void fusedA(const float4* __restrict__ X, const float4* __restrict__ W1,
            const float4* __restrict__ W3, const float4* __restrict__ W2f)
{
    extern __shared__ __align__(128) char smem[];
    const uint32_t sbase = (uint32_t)__cvta_generic_to_shared(smem);
    __shared__ int sTicket;
    const int tid = threadIdx.x;

    for (;;) {
        __syncthreads();
        if (tid == 0) sTicket = atomicAdd(&g_ticket, 1);
        __syncthreads();
        const int t = sTicket;
        if (t >= TK_TOT) return;

        if (t < NE * TK_PER_E) {
            const int e = t / TK_PER_E;
            const int l = t - e * TK_PER_E;
            if (l < 16) {
                // x-conv: rows [l*128, +128) of expert e; 32768 units
                const long long base = ((long long)e * NT * ND + (long long)l * 128 * ND) / 8;
                #pragma unroll 4
                for (int j = 0; j < 128; j++)
                    conv8(X, (__half2*)g_x16, base + j * 256 + tid);
                __threadfence();
                __syncthreads();
                if (tid == 0) atomicAdd(&g_cnt[e], 1);
            } else if (l < 80) {
                // w-conv: cols [cb*64, +64) of w1 & w3, all 2048 k rows
                const int cb = l - 16;
                const int c  = tid & 7;        // 8-col chunk within the 64-col block
                const int r0 = tid >> 3;       // 32 rows per pass
                const long long eb = (long long)e * ND * NH / 8;
                for (int p = 0; p < 64; p++) {
                    const long long u = eb + (long long)(p * 32 + r0) * (NH / 8)
                                        + cb * 8 + c;
                    conv8(W1, (__half2*)g_w1, u);
                    conv8(W3, (__half2*)g_w3, u);
                }
                __threadfence();
                __syncthreads();
                if (tid == 0) atomicAdd(&g_cnt[e], 1);
            } else {
                // gemm13 tile: wait for expert-e conversions
                if (tid == 0) {
                    while (atomicAdd(&g_cnt[e], 0) < 80) __nanosleep(64);
                }
                __syncthreads();
                __threadfence();
                const int tile = l - 80;
                gemm13_tile(e, (tile >> 6) * 128, (tile & 63) * 64, sbase, tid);
            }
        } else {
            // w2-conv tail (ordered before gemm2 by the kernel boundary)
            const long long base = (long long)(t - NE * TK_PER_E) * 8192;
            #pragma unroll 4
            for (int j = 0; j < 32; j++)
                conv8(W2f, (__half2*)g_w2, base + j * 256 + tid);
        }
    }
}

// ---------------- GEMM2: out = h @ w2 (fp32 out, unchanged from R15) ----------------
__global__ __launch_bounds__(256, 2)
void gemm2_out(const __half* __restrict__ Hm, const __half* __restrict__ W2,
               float* __restrict__ Out)
{
    extern __shared__ __align__(128) char smem[];
    const uint32_t sbase = (uint32_t)__cvta_generic_to_shared(smem);
    const int tid = threadIdx.x;
    const int e  = blockIdx.z;
    const int n0 = blockIdx.x * 128;
    const int m0 = blockIdx.y * 128;

    const __half* pA = Hm + (long long)e * NT * NH + (long long)m0 * NH;
    const __half* pB = W2 + (long long)e * NH * ND + n0;

    const int warp = tid >> 5, lane = tid & 31;
    const int wm = (warp & 1) * 64;
    const int wn = (warp >> 1) * 32;

    float acc[4][4][4];
    #pragma unroll
    for (int i = 0; i < 4; i++)
        #pragma unroll
        for (int j = 0; j < 4; j++)
            #pragma unroll
            for (int r = 0; r < 4; r++) acc[i][j][r] = 0.f;

    auto load_stage = [&](int slot, int k0) {
        const uint32_t sb = sbase + slot * 32768;
        #pragma unroll
        for (int i = 0; i < 4; i++) {
            int id = tid + i * 256;
            int row = id >> 3, c = id & 7;
            cp16s(sb + row * 128 + ((c ^ (row & 7)) << 4),
                  pA + (long long)row * NH + k0 + c * 8);
        }
        #pragma unroll
        for (int i = 0; i < 4; i++) {
            int id = tid + i * 256;
            int row = id >> 4, c = id & 15;
            cp16s(sb + 16384 + row * 256 + ((c ^ (row & 7)) << 4),
                  pB + (long long)(k0 + row) * ND + c * 8);
        }
        asm volatile("cp.async.commit_group;" ::: "memory");
    };

    load_stage(0, 0);
    load_stage(1, 64);

    const int NKC = NH / 64;
    for (int ch = 0; ch < NKC; ch++) {
        asm volatile("cp.async.wait_group 1;" ::: "memory");
        __syncthreads();
        if (ch + 2 < NKC) load_stage((ch + 2) % 3, (ch + 2) * 64);
        else asm volatile("cp.async.commit_group;" ::: "memory");

        const uint32_t sb = sbase + (ch % 3) * 32768;
        #pragma unroll
        for (int ks = 0; ks < 4; ks++) {
            uint32_t av[4][4], bv[4][2];
            #pragma unroll
            for (int np = 0; np < 2; np++) {   // B loads first
                int kr = ks * 16 + (lane & 15);
                int nc = (wn >> 3) + np * 2 + (lane >> 4);
                uint32_t bd = sb + 16384 + kr * 256 + ((nc ^ (kr & 7)) << 4);
                uint32_t r[4];
                ldsm4t(r, bd);
                bv[np*2][0] = r[0]; bv[np*2][1] = r[1];
                bv[np*2+1][0] = r[2]; bv[np*2+1][1] = r[3];
            }
            #pragma unroll
            for (int mt = 0; mt < 4; mt++) {
                int row = wm + mt * 16 + (lane & 15);
                int cc  = ks * 2 + (lane >> 4);
                ldsm4(av[mt], sb + row * 128 + ((cc ^ (row & 7)) << 4));
            }
            #pragma unroll
            for (int mt = 0; mt < 4; mt++)
                #pragma unroll
                for (int nt = 0; nt < 4; nt++)
                    mma16816(acc[mt][nt], av[mt], bv[nt]);
        }
    }

    #pragma unroll
    for (int mt = 0; mt < 4; mt++)
        #pragma unroll
        for (int nt = 0; nt < 4; nt++) {
            const int row = m0 + wm + mt * 16 + (lane >> 2);
            const int col = n0 + wn + nt * 8 + (lane & 3) * 2;
            const long long i0 = ((long long)e * NT + row) * ND + col;
            const long long i1 = i0 + 8LL * ND;
            *(float2*)&Out[i0] = make_float2(acc[mt][nt][0], acc[mt][nt][1]);
            *(float2*)&Out[i1] = make_float2(acc[mt][nt][2], acc[mt][nt][3]);
        }
}

// ---------------- launch ----------------
// Inputs: x [E,T,D] fp32, w1 [E,D,H], w2 [E,H,D], w3 [E,D,H]. Output [E,T,D] fp32.
extern "C" void kernel_launch(void* const* d_in, const int* in_sizes, int n_in,
                              void* d_out, int out_size)
{
    const float* x  = (const float*)d_in[0];
    const float* w1 = (const float*)d_in[1];
    const float* w2 = (const float*)d_in[2];
    const float* w3 = (const float*)d_in[3];
    float* out = (float*)d_out;

    cudaFuncSetAttribute(fusedA,    cudaFuncAttributeMaxDynamicSharedMemorySize, 98304);
    cudaFuncSetAttribute(gemm2_out, cudaFuncAttributeMaxDynamicSharedMemorySize, 98304);

    void *w2p, *h16;
    cudaGetSymbolAddress(&w2p, g_w2);
    cudaGetSymbolAddress(&h16, g_h16);

    int nsm = 148;
    cudaDeviceGetAttribute(&nsm, cudaDevAttrMultiProcessorCount, 0);

    reset_kernel<<<1, 32>>>();

    fusedA<<<2 * nsm, 256, 98304>>>((const float4*)x, (const float4*)w1,
                                    (const float4*)w3, (const float4*)w2);

    gemm2_out<<<dim3(ND / 128, NT / 128, NE), 256, 98304>>>(
        (const __half*)h16, (const __half*)w2p, out);
}